// round 2
// baseline (speedup 1.0000x reference)
#include <cuda_runtime.h>

#define N_NODES 200000
#define N_EDGES 6400000
#define HIDDEN  200
#define NHID    6

#define TM      64          // rows per block
#define NPAIR   32          // TM/2 row-pairs
#define PSTR    36          // row-pair stride (float2) -> 72 floats, padded vs 32
#define THREADS 320         // 8 row-groups x 40 col-groups
#define KSLAB   20
#define NSLAB   (HIDDEN / KSLAB)   // 10

// smem layout (bytes)
#define X_BYTES   (2 * HIDDEN * PSTR * 8)       // 115200
#define W_BYTES   (2 * KSLAB * HIDDEN * 4)      // 32000
#define SMEM_BYTES (X_BYTES + W_BYTES + 64*4 + 5*64*4)  // 148736

__device__ float g_agg[N_NODES];

// ---------------- phase A: zero the aggregation buffer ----------------
__global__ void k_zero() {
    int i = blockIdx.x * blockDim.x + threadIdx.x;
    if (i < N_NODES) g_agg[i] = 0.0f;
}

// ---------------- phase B: edge scatter-add (atomics into L2) ----------------
// edge_index is INT32: jax coerces the requested int64 to int32 because
// jax_enable_x64 is off in the reference environment.
__global__ void k_scatter(const float* __restrict__ x, const int* __restrict__ ei) {
    int i = blockIdx.x * blockDim.x + threadIdx.x;      // quad-edge index
    if (i < N_EDGES / 4) {
        const int4 s = reinterpret_cast<const int4*>(ei)[i];
        const int4 d = reinterpret_cast<const int4*>(ei + N_EDGES)[i];
        atomicAdd(&g_agg[d.x], x[s.x]);
        atomicAdd(&g_agg[d.y], x[s.y]);
        atomicAdd(&g_agg[d.z], x[s.z]);
        atomicAdd(&g_agg[d.w], x[s.w]);
    }
}

// ---------------- helpers ----------------
__device__ __forceinline__ void cp16(void* sdst, const void* gsrc) {
    unsigned saddr = (unsigned)__cvta_generic_to_shared(sdst);
    asm volatile("cp.async.cg.shared.global [%0], [%1], 16;\n" :: "r"(saddr), "l"(gsrc));
}
__device__ __forceinline__ void cp_commit() { asm volatile("cp.async.commit_group;"); }
__device__ __forceinline__ void cp_wait1()  { asm volatile("cp.async.wait_group 1;"); }
__device__ __forceinline__ void cp_wait0()  { asm volatile("cp.async.wait_group 0;"); }

__device__ __forceinline__ unsigned long long pack2(float w) {
    unsigned long long r;
    asm("mov.b64 %0, {%1, %1};" : "=l"(r) : "f"(w));
    return r;
}
__device__ __forceinline__ void fma2(unsigned long long& acc, unsigned long long a, unsigned long long b) {
    asm("fma.rn.f32x2 %0, %1, %2, %0;" : "+l"(acc) : "l"(a), "l"(b));
}
__device__ __forceinline__ float2 unpack2(unsigned long long v) {
    float2 r;
    asm("mov.b64 {%0, %1}, %2;" : "=f"(r.x), "=f"(r.y) : "l"(v));
    return r;
}

// ---------------- phase C: fused GraphConv-scalar + 8-layer MLP + sigmoid ----------------
__global__ void __launch_bounds__(THREADS, 1) k_mlp(
    const float* __restrict__ x,
    const float* __restrict__ w_rel, const float* __restrict__ b_rel,
    const float* __restrict__ w_root,
    const float* __restrict__ w_in,  const float* __restrict__ b_in,
    const float* __restrict__ w_hid, const float* __restrict__ b_hid,
    const float* __restrict__ w_out, const float* __restrict__ b_out,
    float* __restrict__ out)
{
    extern __shared__ char smem[];
    float2* Xb0   = reinterpret_cast<float2*>(smem);                 // [HIDDEN][PSTR]
    float2* Xb1   = Xb0 + HIDDEN * PSTR;
    float*  Wb    = reinterpret_cast<float*>(smem + X_BYTES);        // [2][KSLAB*HIDDEN]
    float*  h0s   = reinterpret_cast<float*>(smem + X_BYTES + W_BYTES);   // [64]
    float*  zpart = h0s + 64;                                        // [5][64]

    const int tid = threadIdx.x;
    const int rg  = tid & 7;       // row group: rows rg*8 .. rg*8+7 (pairs rg*4..rg*4+3)
    const int cg  = tid >> 3;      // col group: cols cg, cg+40, ..., cg+160
    const int row0 = blockIdx.x * TM;

    // h0 = agg*w_rel + b_rel + x*w_root  (all 1x1 weights)
    if (tid < TM) {
        int r = row0 + tid;
        h0s[tid] = g_agg[r] * w_rel[0] + b_rel[0] + x[r] * w_root[0];
    }
    // prefetch weight slab 0 of hidden layer 0
    {
        const float* src = w_hid;   // layer 0, slab 0
        for (int c = tid; c < KSLAB * HIDDEN / 4; c += THREADS)
            cp16(Wb + c * 4, src + c * 4);
        cp_commit();
    }
    __syncthreads();

    // input layer: X0[k][pair] = relu(h0 * w_in[k] + b_in[k])
    for (int t = tid; t < HIDDEN * NPAIR; t += THREADS) {
        int k = t >> 5, p = t & 31;
        float wk = w_in[k], bk = b_in[k];
        float2 v;
        v.x = fmaxf(fmaf(h0s[2 * p],     wk, bk), 0.0f);
        v.y = fmaxf(fmaf(h0s[2 * p + 1], wk, bk), 0.0f);
        Xb0[k * PSTR + p] = v;
    }

    int cur = 0;
    for (int l = 0; l < NHID; ++l) {
        unsigned long long acc[4][5];
        #pragma unroll
        for (int rr = 0; rr < 4; ++rr)
            #pragma unroll
            for (int m = 0; m < 5; ++m) acc[rr][m] = 0ull;

        const float2* Xc = cur ? Xb1 : Xb0;
        float2*       Xn = cur ? Xb0 : Xb1;
        const float*  wl = w_hid + l * HIDDEN * HIDDEN;

        for (int s = 0; s < NSLAB; ++s) {
            __syncthreads();   // (a) buffer (s+1)&1 free for refill
            bool last = (l == NHID - 1) && (s == NSLAB - 1);
            if (!last) {
                const float* nsrc = (s < NSLAB - 1) ? (wl + (s + 1) * KSLAB * HIDDEN)
                                                    : (w_hid + (l + 1) * HIDDEN * HIDDEN);
                float* ndst = Wb + ((s + 1) & 1) * (KSLAB * HIDDEN);
                for (int c = tid; c < KSLAB * HIDDEN / 4; c += THREADS)
                    cp16(ndst + c * 4, nsrc + c * 4);
                cp_commit();
                cp_wait1();    // slab s complete (only slab s+1 may stay pending)
            } else {
                cp_wait0();
            }
            __syncthreads();   // (b) slab s visible to all

            const float* wsp = Wb + (s & 1) * (KSLAB * HIDDEN) + cg;
            const float2* xps = Xc + (size_t)s * KSLAB * PSTR + rg * 4;

            #pragma unroll
            for (int kk = 0; kk < KSLAB; ++kk) {
                ulonglong2 xa = *reinterpret_cast<const ulonglong2*>(xps + kk * PSTR);
                ulonglong2 xb = *reinterpret_cast<const ulonglong2*>(xps + kk * PSTR + 2);
                unsigned long long xr0 = xa.x, xr1 = xa.y, xr2 = xb.x, xr3 = xb.y;
                #pragma unroll
                for (int m = 0; m < 5; ++m) {
                    unsigned long long wp = pack2(wsp[kk * HIDDEN + 40 * m]);
                    fma2(acc[0][m], xr0, wp);
                    fma2(acc[1][m], xr1, wp);
                    fma2(acc[2][m], xr2, wp);
                    fma2(acc[3][m], xr3, wp);
                }
            }
        }

        // epilogue: bias + relu, store to the other X buffer
        #pragma unroll
        for (int m = 0; m < 5; ++m) {
            int j = cg + 40 * m;
            float bj = b_hid[l * HIDDEN + j];
            float2 o0 = unpack2(acc[0][m]);
            float2 o1 = unpack2(acc[1][m]);
            float2 o2 = unpack2(acc[2][m]);
            float2 o3 = unpack2(acc[3][m]);
            float4 v0 = make_float4(fmaxf(o0.x + bj, 0.f), fmaxf(o0.y + bj, 0.f),
                                    fmaxf(o1.x + bj, 0.f), fmaxf(o1.y + bj, 0.f));
            float4 v1 = make_float4(fmaxf(o2.x + bj, 0.f), fmaxf(o2.y + bj, 0.f),
                                    fmaxf(o3.x + bj, 0.f), fmaxf(o3.y + bj, 0.f));
            float2* xn = Xn + j * PSTR + rg * 4;
            *reinterpret_cast<float4*>(xn)     = v0;
            *reinterpret_cast<float4*>(xn + 2) = v1;
        }
        cur ^= 1;
    }
    __syncthreads();   // final activations ready

    // output layer: z[r] = sum_k X[k][r] * w_out[k] + b_out; out = sigmoid(z)
    {
        const float* Xf = reinterpret_cast<const float*>(cur ? Xb1 : Xb0);
        int part = tid >> 6;        // 0..4
        int r    = tid & 63;
        float sum = 0.0f;
        int k0 = part * 40;
        #pragma unroll 8
        for (int k = k0; k < k0 + 40; ++k)
            sum = fmaf(Xf[k * (2 * PSTR) + r], w_out[k], sum);
        zpart[part * 64 + r] = sum;
    }
    __syncthreads();
    if (tid < TM) {
        float z = zpart[tid] + zpart[64 + tid] + zpart[128 + tid]
                + zpart[192 + tid] + zpart[256 + tid] + b_out[0];
        out[row0 + tid] = 1.0f / (1.0f + expf(-z));
    }
}

// ---------------- launch ----------------
extern "C" void kernel_launch(void* const* d_in, const int* in_sizes, int n_in,
                              void* d_out, int out_size)
{
    const float* x      = (const float*)d_in[0];
    const int*   ei     = (const int*)d_in[1];      // int32! (jax x64 disabled)
    const float* w_rel  = (const float*)d_in[2];
    const float* b_rel  = (const float*)d_in[3];
    const float* w_root = (const float*)d_in[4];
    const float* w_in   = (const float*)d_in[5];
    const float* b_in   = (const float*)d_in[6];
    const float* w_hid  = (const float*)d_in[7];
    const float* b_hid  = (const float*)d_in[8];
    const float* w_out  = (const float*)d_in[9];
    const float* b_out  = (const float*)d_in[10];
    float*       out    = (float*)d_out;

    cudaFuncSetAttribute(k_mlp, cudaFuncAttributeMaxDynamicSharedMemorySize, SMEM_BYTES);

    k_zero<<<(N_NODES + 255) / 256, 256>>>();
    k_scatter<<<(N_EDGES / 4 + 255) / 256, 256>>>(x, ei);
    k_mlp<<<N_NODES / TM, THREADS, SMEM_BYTES>>>(
        x, w_rel, b_rel, w_root, w_in, b_in, w_hid, b_hid, w_out, b_out, out);
}